// round 9
// baseline (speedup 1.0000x reference)
#include <cuda_runtime.h>
#include <cub/cub.cuh>

#define BB 8
#define NN 2048
#define MM 2048
#define DIN 256
#define EE 128
#define LALPHA 0.01f
#define NCHUNK 128
#define CHUNK 16            // MM / NCHUNK

#define GEMM_BLOCKS 256
#define ATT1_BLOCKS 2048    // B*N / 8 rows-per-block

// ---------------- scratch (device globals; no allocation allowed) ----------------
__device__ float g_v1[DIN];
__device__ float g_att2[BB * MM];
__device__ float g_E1p[BB * NN], g_E1n[BB * NN], g_key[BB * NN];   // key = -att1
__device__ float g_F2p[BB * MM], g_F2n[BB * MM];
__device__ float g_Wh2[BB * MM * EE];
__device__ float g_sortv[BB * MM];
__device__ int   g_sortidx[BB * MM];
__device__ float g_chP[BB * NCHUNK * EE], g_chN[BB * NCHUNK * EE];
__device__ float g_chPs[BB * NCHUNK], g_chNs[BB * NCHUNK];
__device__ float g_offP[BB * NCHUNK * EE], g_offN[BB * NCHUNK * EE];
__device__ float g_offPs[BB * NCHUNK], g_offNs[BB * NCHUNK];
__device__ float g_sufP[BB * (MM + 1) * EE];   // suffix sums of F2p*Wh2 in sorted order
__device__ float g_preN[BB * (MM + 1) * EE];   // prefix sums of F2n*Wh2 in sorted order
__device__ float g_sufPs[BB * (MM + 1)], g_preNs[BB * (MM + 1)];

// ---------------- 1. v1 = W1 @ a1_top ----------------
__global__ void k_v(const float* __restrict__ W1, const float* __restrict__ a1) {
    int d = threadIdx.x;   // 0..255
    float s1 = 0.f;
    #pragma unroll 8
    for (int e = 0; e < EE; e++) s1 += W1[d * EE + e] * a1[e];
    g_v1[d] = s1;
}

// ---------------- 2. Wh2 GEMM (blocks 0..255) + att1 (blocks 256..2303) ----------------
__global__ void __launch_bounds__(256) k_wh2(const float* __restrict__ in2,
                                             const float* __restrict__ W1,
                                             const float* __restrict__ mask,
                                             const float* __restrict__ a1,
                                             const float* __restrict__ in1) {
    __shared__ float As[64 * 32];
    __shared__ float Bs[32 * 128];
    int tid = threadIdx.x;

    if (blockIdx.x >= GEMM_BLOCKS) {
        // ---- att1 path: 8 warps, one row each ----
        int w    = (blockIdx.x - GEMM_BLOCKS) * 8 + (tid >> 5);   // 0 .. B*N-1
        int lane = tid & 31;
        const float4* p  = (const float4*)(in1 + (size_t)w * DIN);
        const float4* v4 = (const float4*)g_v1;
        float acc = 0.f;
        #pragma unroll
        for (int i = 0; i < 2; i++) {
            float4 x  = p[lane + 32 * i];
            float4 vv = v4[lane + 32 * i];
            acc += x.x * vv.x + x.y * vv.y + x.z * vv.z + x.w * vv.w;
        }
        #pragma unroll
        for (int o = 16; o > 0; o >>= 1) acc += __shfl_xor_sync(0xffffffffu, acc, o);
        if (lane == 0) {
            g_E1p[w] = expf(acc);
            g_E1n[w] = expf(LALPHA * acc);
            g_key[w] = -acc;
        }
        return;
    }

    // ---- GEMM path ----
    int tx = tid & 31;    // column group -> cols tx*4..tx*4+3
    int ty = tid >> 5;    // row group   -> rows ty*8..ty*8+7 (one warp per ty)
    int row0 = blockIdx.x * 64;
    float acc[8][4];
    #pragma unroll
    for (int r = 0; r < 8; r++)
        #pragma unroll
        for (int c = 0; c < 4; c++) acc[r][c] = 0.f;

    for (int k0 = 0; k0 < DIN; k0 += 32) {
        #pragma unroll
        for (int i = tid; i < 512; i += 256) {
            int r = i >> 3, kq = i & 7;
            ((float4*)As)[i] = *(const float4*)(in2 + (size_t)(row0 + r) * DIN + k0 + kq * 4);
        }
        #pragma unroll
        for (int i = tid; i < 1024; i += 256) {
            ((float4*)Bs)[i] = ((const float4*)(W1 + (size_t)k0 * EE))[i];
        }
        __syncthreads();
        #pragma unroll
        for (int kk = 0; kk < 32; kk += 4) {
            float4 b0 = ((float4*)Bs)[(kk + 0) * 32 + tx];
            float4 b1 = ((float4*)Bs)[(kk + 1) * 32 + tx];
            float4 b2 = ((float4*)Bs)[(kk + 2) * 32 + tx];
            float4 b3 = ((float4*)Bs)[(kk + 3) * 32 + tx];
            #pragma unroll
            for (int r = 0; r < 8; r++) {
                float4 a4 = *(float4*)&As[(ty * 8 + r) * 32 + kk];   // warp-broadcast
                acc[r][0] += a4.x * b0.x + a4.y * b1.x + a4.z * b2.x + a4.w * b3.x;
                acc[r][1] += a4.x * b0.y + a4.y * b1.y + a4.z * b2.y + a4.w * b3.y;
                acc[r][2] += a4.x * b0.z + a4.y * b1.z + a4.z * b2.z + a4.w * b3.z;
                acc[r][3] += a4.x * b0.w + a4.y * b1.w + a4.z * b2.w + a4.w * b3.w;
            }
        }
        __syncthreads();
    }
    // epilogue: store Wh2 and compute att2 = Wh2 . a1[128:]
    float4 va = *(const float4*)(a1 + EE + tx * 4);
    #pragma unroll
    for (int r = 0; r < 8; r++) {
        int row = row0 + ty * 8 + r;
        *(float4*)(g_Wh2 + (size_t)row * EE + tx * 4) =
            make_float4(acc[r][0], acc[r][1], acc[r][2], acc[r][3]);
        float part = acc[r][0] * va.x + acc[r][1] * va.y + acc[r][2] * va.z + acc[r][3] * va.w;
        #pragma unroll
        for (int o = 16; o > 0; o >>= 1) part += __shfl_xor_sync(0xffffffffu, part, o);
        if (tx == 0) {
            int b = row >> 11, m = row & (MM - 1);
            float mk = mask[b * MM + m];
            g_att2[row] = part;
            g_F2p[row] = expf(part + mk);
            g_F2n[row] = expf(LALPHA * part + mk);
        }
    }
}

// ---------------- 3. per-batch radix sort of att2 (with index) ----------------
__global__ void __launch_bounds__(512) k_sort() {
    typedef cub::BlockRadixSort<float, 512, 4, int> Sorter;
    __shared__ typename Sorter::TempStorage tmp;
    int b = blockIdx.x;
    float key[4];
    int   val[4];
    #pragma unroll
    for (int i = 0; i < 4; i++) {
        int idx = threadIdx.x * 4 + i;
        key[i] = g_att2[b * MM + idx];
        val[i] = idx;
    }
    Sorter(tmp).Sort(key, val);
    #pragma unroll
    for (int i = 0; i < 4; i++) {
        int idx = threadIdx.x * 4 + i;
        g_sortv[b * MM + idx]   = key[i];
        g_sortidx[b * MM + idx] = val[i];
    }
}

// ---------------- staging helper: load one sorted chunk into smem ----------------
// Flat float4 gather: 4 independent coalesced LDG.128 per thread, no chain.
__device__ __forceinline__ void stage_chunk(int b, int c, int tid,
                                            float (*sw)[EE], float* sfp, float* sfn,
                                            int* sm) {
    int base = b * MM + c * CHUNK;
    if (tid < CHUNK) sm[tid] = g_sortidx[base + tid];
    __syncthreads();
    #pragma unroll
    for (int i = tid; i < CHUNK * 32; i += 128) {
        int row = i >> 5, c4 = i & 31;
        ((float4*)&sw[row][0])[c4] =
            ((const float4*)(g_Wh2 + (size_t)(b * MM + sm[row]) * EE))[c4];
    }
    if (tid < CHUNK) {
        sfp[tid] = g_F2p[b * MM + sm[tid]];
        sfn[tid] = g_F2n[b * MM + sm[tid]];
    }
    __syncthreads();
}

// ---------------- 4a. chunk partial sums (sorted order, fp32, smem-staged) ----------
__global__ void __launch_bounds__(EE) k_chunksum() {
    __shared__ float sw[CHUNK][EE];
    __shared__ float sfp[CHUNK], sfn[CHUNK];
    __shared__ int   sm[CHUNK];
    int b = blockIdx.y, c = blockIdx.x, e = threadIdx.x;
    stage_chunk(b, c, e, sw, sfp, sfn, sm);
    float aP0 = 0.f, aP1 = 0.f, aP2 = 0.f, aP3 = 0.f;
    float aN0 = 0.f, aN1 = 0.f, aN2 = 0.f, aN3 = 0.f;
    #pragma unroll
    for (int j = 0; j < CHUNK; j += 4) {
        aP0 += sfp[j + 0] * sw[j + 0][e];  aN0 += sfn[j + 0] * sw[j + 0][e];
        aP1 += sfp[j + 1] * sw[j + 1][e];  aN1 += sfn[j + 1] * sw[j + 1][e];
        aP2 += sfp[j + 2] * sw[j + 2][e];  aN2 += sfn[j + 2] * sw[j + 2][e];
        aP3 += sfp[j + 3] * sw[j + 3][e];  aN3 += sfn[j + 3] * sw[j + 3][e];
    }
    g_chP[(b * NCHUNK + c) * EE + e] = (aP0 + aP1) + (aP2 + aP3);
    g_chN[(b * NCHUNK + c) * EE + e] = (aN0 + aN1) + (aN2 + aN3);
    if (e == 0) {
        float sP = 0.f, sN = 0.f;
        #pragma unroll
        for (int j = 0; j < CHUNK; j++) { sP += sfp[j]; sN += sfn[j]; }
        g_chPs[b * NCHUNK + c] = sP;
        g_chNs[b * NCHUNK + c] = sN;
    }
}

// ---------------- 4b. chunk-level offsets (fp32; positive sums) ----------------
__global__ void k_offsets() {
    int b = blockIdx.x, e = threadIdx.x;
    float run = 0.f;
    for (int c = 0; c < NCHUNK; c++) {
        g_offN[(b * NCHUNK + c) * EE + e] = run;
        run += g_chN[(b * NCHUNK + c) * EE + e];
    }
    g_preN[((size_t)b * (MM + 1) + MM) * EE + e] = run;
    float runP = 0.f;
    for (int c = NCHUNK - 1; c >= 0; c--) {
        g_offP[(b * NCHUNK + c) * EE + e] = runP;
        runP += g_chP[(b * NCHUNK + c) * EE + e];
    }
    g_sufP[((size_t)b * (MM + 1) + MM) * EE + e] = 0.f;
    if (e == 0) {
        float r = 0.f;
        for (int c = 0; c < NCHUNK; c++) { g_offNs[b * NCHUNK + c] = r; r += g_chNs[b * NCHUNK + c]; }
        g_preNs[b * (MM + 1) + MM] = r;
        float rp = 0.f;
        for (int c = NCHUNK - 1; c >= 0; c--) { g_offPs[b * NCHUNK + c] = rp; rp += g_chPs[b * NCHUNK + c]; }
        g_sufPs[b * (MM + 1) + MM] = 0.f;
    }
}

// ---------------- 4c. fine-grained prefix (N) and suffix (P) sums (fp32) ------------
__global__ void __launch_bounds__(EE) k_scan() {
    __shared__ float sw[CHUNK][EE];
    __shared__ float sfp[CHUNK], sfn[CHUNK];
    __shared__ int   sm[CHUNK];
    int b = blockIdx.y, c = blockIdx.x, e = threadIdx.x;
    stage_chunk(b, c, e, sw, sfp, sfn, sm);

    // forward pass: prefix of F2n * Wh2
    {
        float runN  = g_offN[(b * NCHUNK + c) * EE + e];
        float runNs = (e == 0) ? g_offNs[b * NCHUNK + c] : 0.f;
        #pragma unroll
        for (int j = 0; j < CHUNK; j++) {
            int k = c * CHUNK + j;
            g_preN[((size_t)b * (MM + 1) + k) * EE + e] = runN;
            if (e == 0) g_preNs[b * (MM + 1) + k] = runNs;
            runN += sfn[j] * sw[j][e];
            if (e == 0) runNs += sfn[j];
        }
    }
    // backward pass: suffix of F2p * Wh2
    {
        float runP  = g_offP[(b * NCHUNK + c) * EE + e];
        float runPs = (e == 0) ? g_offPs[b * NCHUNK + c] : 0.f;
        #pragma unroll
        for (int j = CHUNK - 1; j >= 0; j--) {
            int k = c * CHUNK + j;
            runP += sfp[j] * sw[j][e];
            if (e == 0) runPs += sfp[j];
            g_sufP[((size_t)b * (MM + 1) + k) * EE + e] = runP;
            if (e == 0) g_sufPs[b * (MM + 1) + k] = runPs;
        }
    }
}

// ---------------- 5. fused rank + context + probs (8 rows per block) ----------------
__global__ void __launch_bounds__(512) k_rankprobs(float* __restrict__ out_ctx,
                                                   float* __restrict__ out_p) {
    __shared__ int   sk[8];
    __shared__ float sc1[8], sc2[8], skey[8];
    int g = blockIdx.x;            // 0 .. B*N/8 - 1
    int row0 = g * 8;
    int b = row0 >> 11;
    int tid = threadIdx.x;
    if (tid < 8) {
        int row = row0 + tid;
        float key = g_key[row];
        const float* sv = g_sortv + b * MM;
        int lo = 0, hi = MM;       // first index with sv[idx] > key
        while (lo < hi) {
            int mid = (lo + hi) >> 1;
            if (sv[mid] > key) hi = mid; else lo = mid + 1;
        }
        float E1p = g_E1p[row], E1n = g_E1n[row];
        float S = E1p * g_sufPs[b * (MM + 1) + lo] + E1n * g_preNs[b * (MM + 1) + lo];
        float invS = 1.f / S;
        sk[tid] = lo;
        sc1[tid] = E1p * invS;
        sc2[tid] = E1n * invS;
        skey[tid] = key;
    }
    __syncthreads();
    // context: 4 rows per pass, 2 passes
    {
        int e = tid & (EE - 1);
        int rb = tid >> 7;         // 0..3
        #pragma unroll
        for (int it = 0; it < 2; it++) {
            int r = it * 4 + rb;
            int row = row0 + r;
            int k = sk[r];
            float num = sc1[r] * g_sufP[((size_t)b * (MM + 1) + k) * EE + e]
                      + sc2[r] * g_preN[((size_t)b * (MM + 1) + k) * EE + e];
            out_ctx[(size_t)row * EE + e] = num;
        }
    }
    // probs: per-batch vectors held in registers, 8 output rows
    const float4 tv = ((const float4*)(g_att2 + b * MM))[tid];
    const float4 pv = ((const float4*)(g_F2p + b * MM))[tid];
    const float4 nv = ((const float4*)(g_F2n + b * MM))[tid];
    #pragma unroll
    for (int r = 0; r < 8; r++) {
        int row = row0 + r;
        float key = skey[r], c1 = sc1[r], c2 = sc2[r];
        float4 o;
        o.x = (tv.x > key) ? c1 * pv.x : c2 * nv.x;
        o.y = (tv.y > key) ? c1 * pv.y : c2 * nv.y;
        o.z = (tv.z > key) ? c1 * pv.z : c2 * nv.z;
        o.w = (tv.w > key) ? c1 * pv.w : c2 * nv.w;
        ((float4*)(out_p + (size_t)row * MM))[tid] = o;
    }
}

// ---------------- launch ----------------
extern "C" void kernel_launch(void* const* d_in, const int* in_sizes, int n_in,
                              void* d_out, int out_size) {
    const float* in1  = (const float*)d_in[0];   // (8,2048,256)
    const float* in2  = (const float*)d_in[1];   // (8,2048,256)
    const float* mask = (const float*)d_in[2];   // (8,1,2048)
    const float* W1   = (const float*)d_in[3];   // (256,128)
    const float* a1   = (const float*)d_in[4];   // (256,1)
    float* out = (float*)d_out;
    float* out_ctx   = out;                              // (8,2048,128)
    float* out_probs = out + (size_t)BB * NN * EE;       // (8,2048,2048)

    k_v<<<1, 256>>>(W1, a1);
    k_wh2<<<GEMM_BLOCKS + ATT1_BLOCKS, 256>>>(in2, W1, mask, a1, in1);
    k_sort<<<BB, 512>>>();
    dim3 gc(NCHUNK, BB);
    k_chunksum<<<gc, EE>>>();
    k_offsets<<<BB, EE>>>();
    k_scan<<<gc, EE>>>();
    k_rankprobs<<<BB * NN / 8, 512>>>(out_ctx, out_probs);
}

// round 10
// speedup vs baseline: 1.4420x; 1.4420x over previous
#include <cuda_runtime.h>
#include <cub/cub.cuh>

#define BB 8
#define NN 2048
#define MM 2048
#define DIN 256
#define EE 128
#define LALPHA 0.01f
#define NCHUNK 128
#define CHUNK 16            // MM / NCHUNK

#define GEMM_BLOCKS 256
#define ATT1_BLOCKS 2048    // B*N / 8 rows-per-block

// ---------------- scratch (device globals; no allocation allowed) ----------------
__device__ float g_v1[DIN];
__device__ float g_att2[BB * MM];
__device__ float g_E1p[BB * NN], g_E1n[BB * NN], g_key[BB * NN];   // key = -att1
__device__ float g_F2p[BB * MM], g_F2n[BB * MM];
__device__ float g_Wh2[BB * MM * EE];
__device__ float g_sortv[BB * MM];
__device__ int   g_sortidx[BB * MM];
__device__ float g_chP[BB * NCHUNK * EE], g_chN[BB * NCHUNK * EE];
__device__ float g_chPs[BB * NCHUNK], g_chNs[BB * NCHUNK];
__device__ float g_offP[BB * NCHUNK * EE], g_offN[BB * NCHUNK * EE];
__device__ float g_offPs[BB * NCHUNK], g_offNs[BB * NCHUNK];
__device__ float g_sufP[BB * (MM + 1) * EE];   // suffix sums of F2p*Wh2 in sorted order
__device__ float g_preN[BB * (MM + 1) * EE];   // prefix sums of F2n*Wh2 in sorted order
__device__ float g_sufPs[BB * (MM + 1)], g_preNs[BB * (MM + 1)];

// ---------------- 1. v1 = W1 @ a1_top ----------------
__global__ void k_v(const float* __restrict__ W1, const float* __restrict__ a1) {
    int d = threadIdx.x;   // 0..255
    float s1 = 0.f;
    #pragma unroll 8
    for (int e = 0; e < EE; e++) s1 += W1[d * EE + e] * a1[e];
    g_v1[d] = s1;
}

// ---------------- 2. Wh2 GEMM via fma.f32x2 (blocks 0..255) + att1 (256..2303) -------
__global__ void __launch_bounds__(256) k_wh2(const float* __restrict__ in2,
                                             const float* __restrict__ W1,
                                             const float* __restrict__ mask,
                                             const float* __restrict__ a1,
                                             const float* __restrict__ in1) {
    __shared__ float As[64 * 32];
    __shared__ float Bs[32 * 128];
    int tid = threadIdx.x;

    if (blockIdx.x >= GEMM_BLOCKS) {
        // ---- att1 path: 8 warps, one row each ----
        int w    = (blockIdx.x - GEMM_BLOCKS) * 8 + (tid >> 5);   // 0 .. B*N-1
        int lane = tid & 31;
        const float4* p  = (const float4*)(in1 + (size_t)w * DIN);
        const float4* v4 = (const float4*)g_v1;
        float acc = 0.f;
        #pragma unroll
        for (int i = 0; i < 2; i++) {
            float4 x  = p[lane + 32 * i];
            float4 vv = v4[lane + 32 * i];
            acc += x.x * vv.x + x.y * vv.y + x.z * vv.z + x.w * vv.w;
        }
        #pragma unroll
        for (int o = 16; o > 0; o >>= 1) acc += __shfl_xor_sync(0xffffffffu, acc, o);
        if (lane == 0) {
            g_E1p[w] = expf(acc);
            g_E1n[w] = expf(LALPHA * acc);
            g_key[w] = -acc;
        }
        return;
    }

    // ---- GEMM path: 64 rows x 128 cols, K=256, packed f32x2 accumulators ----
    int tx = tid & 31;    // column group -> cols tx*4..tx*4+3
    int ty = tid >> 5;    // row group   -> rows ty*8..ty*8+7 (one warp per ty)
    int row0 = blockIdx.x * 64;
    uint64_t acc01[8], acc23[8];   // packed (col0,col1) and (col2,col3) per row
    #pragma unroll
    for (int r = 0; r < 8; r++) { acc01[r] = 0ull; acc23[r] = 0ull; }

    for (int k0 = 0; k0 < DIN; k0 += 32) {
        #pragma unroll
        for (int i = tid; i < 512; i += 256) {
            int r = i >> 3, kq = i & 7;
            ((float4*)As)[i] = *(const float4*)(in2 + (size_t)(row0 + r) * DIN + k0 + kq * 4);
        }
        #pragma unroll
        for (int i = tid; i < 1024; i += 256) {
            ((float4*)Bs)[i] = ((const float4*)(W1 + (size_t)k0 * EE))[i];
        }
        __syncthreads();
        const uint64_t* Bs64 = (const uint64_t*)Bs;   // 32 rows x 64 packed-pairs
        #pragma unroll
        for (int kk = 0; kk < 32; kk += 4) {
            uint64_t b01[4], b23[4];
            #pragma unroll
            for (int q = 0; q < 4; q++) {
                b01[q] = Bs64[(kk + q) * 64 + tx * 2 + 0];
                b23[q] = Bs64[(kk + q) * 64 + tx * 2 + 1];
            }
            #pragma unroll
            for (int r = 0; r < 8; r++) {
                float4 a4 = *(float4*)&As[(ty * 8 + r) * 32 + kk];   // warp-broadcast
                uint64_t aa;
                asm("mov.b64 %0, {%1, %1};" : "=l"(aa) : "f"(a4.x));
                asm("fma.rn.f32x2 %0, %1, %2, %0;" : "+l"(acc01[r]) : "l"(aa), "l"(b01[0]));
                asm("fma.rn.f32x2 %0, %1, %2, %0;" : "+l"(acc23[r]) : "l"(aa), "l"(b23[0]));
                asm("mov.b64 %0, {%1, %1};" : "=l"(aa) : "f"(a4.y));
                asm("fma.rn.f32x2 %0, %1, %2, %0;" : "+l"(acc01[r]) : "l"(aa), "l"(b01[1]));
                asm("fma.rn.f32x2 %0, %1, %2, %0;" : "+l"(acc23[r]) : "l"(aa), "l"(b23[1]));
                asm("mov.b64 %0, {%1, %1};" : "=l"(aa) : "f"(a4.z));
                asm("fma.rn.f32x2 %0, %1, %2, %0;" : "+l"(acc01[r]) : "l"(aa), "l"(b01[2]));
                asm("fma.rn.f32x2 %0, %1, %2, %0;" : "+l"(acc23[r]) : "l"(aa), "l"(b23[2]));
                asm("mov.b64 %0, {%1, %1};" : "=l"(aa) : "f"(a4.w));
                asm("fma.rn.f32x2 %0, %1, %2, %0;" : "+l"(acc01[r]) : "l"(aa), "l"(b01[3]));
                asm("fma.rn.f32x2 %0, %1, %2, %0;" : "+l"(acc23[r]) : "l"(aa), "l"(b23[3]));
            }
        }
        __syncthreads();
    }
    // epilogue: unpack, store Wh2, and compute att2 = Wh2 . a1[128:]
    float4 va = *(const float4*)(a1 + EE + tx * 4);
    #pragma unroll
    for (int r = 0; r < 8; r++) {
        float c0, c1, c2, c3;
        asm("mov.b64 {%0, %1}, %2;" : "=f"(c0), "=f"(c1) : "l"(acc01[r]));
        asm("mov.b64 {%0, %1}, %2;" : "=f"(c2), "=f"(c3) : "l"(acc23[r]));
        int row = row0 + ty * 8 + r;
        *(float4*)(g_Wh2 + (size_t)row * EE + tx * 4) = make_float4(c0, c1, c2, c3);
        float part = c0 * va.x + c1 * va.y + c2 * va.z + c3 * va.w;
        #pragma unroll
        for (int o = 16; o > 0; o >>= 1) part += __shfl_xor_sync(0xffffffffu, part, o);
        if (tx == 0) {
            int b = row >> 11, m = row & (MM - 1);
            float mk = mask[b * MM + m];
            g_att2[row] = part;
            g_F2p[row] = expf(part + mk);
            g_F2n[row] = expf(LALPHA * part + mk);
        }
    }
}

// ---------------- 3. per-batch radix sort of att2 (with index) ----------------
__global__ void __launch_bounds__(512) k_sort() {
    typedef cub::BlockRadixSort<float, 512, 4, int> Sorter;
    __shared__ typename Sorter::TempStorage tmp;
    int b = blockIdx.x;
    float key[4];
    int   val[4];
    #pragma unroll
    for (int i = 0; i < 4; i++) {
        int idx = threadIdx.x * 4 + i;
        key[i] = g_att2[b * MM + idx];
        val[i] = idx;
    }
    Sorter(tmp).Sort(key, val);
    #pragma unroll
    for (int i = 0; i < 4; i++) {
        int idx = threadIdx.x * 4 + i;
        g_sortv[b * MM + idx]   = key[i];
        g_sortidx[b * MM + idx] = val[i];
    }
}

// ---------------- staging helper: load one sorted chunk into smem ----------------
// Flat float4 gather: 4 independent coalesced LDG.128 per thread, no chain.
__device__ __forceinline__ void stage_chunk(int b, int c, int tid,
                                            float (*sw)[EE], float* sfp, float* sfn,
                                            int* sm) {
    int base = b * MM + c * CHUNK;
    if (tid < CHUNK) sm[tid] = g_sortidx[base + tid];
    __syncthreads();
    #pragma unroll
    for (int i = tid; i < CHUNK * 32; i += 128) {
        int row = i >> 5, c4 = i & 31;
        ((float4*)&sw[row][0])[c4] =
            ((const float4*)(g_Wh2 + (size_t)(b * MM + sm[row]) * EE))[c4];
    }
    if (tid < CHUNK) {
        sfp[tid] = g_F2p[b * MM + sm[tid]];
        sfn[tid] = g_F2n[b * MM + sm[tid]];
    }
    __syncthreads();
}

// ---------------- 4a. chunk partial sums (sorted order, fp32, smem-staged) ----------
__global__ void __launch_bounds__(EE) k_chunksum() {
    __shared__ float sw[CHUNK][EE];
    __shared__ float sfp[CHUNK], sfn[CHUNK];
    __shared__ int   sm[CHUNK];
    int b = blockIdx.y, c = blockIdx.x, e = threadIdx.x;
    stage_chunk(b, c, e, sw, sfp, sfn, sm);
    float aP0 = 0.f, aP1 = 0.f, aP2 = 0.f, aP3 = 0.f;
    float aN0 = 0.f, aN1 = 0.f, aN2 = 0.f, aN3 = 0.f;
    #pragma unroll
    for (int j = 0; j < CHUNK; j += 4) {
        aP0 += sfp[j + 0] * sw[j + 0][e];  aN0 += sfn[j + 0] * sw[j + 0][e];
        aP1 += sfp[j + 1] * sw[j + 1][e];  aN1 += sfn[j + 1] * sw[j + 1][e];
        aP2 += sfp[j + 2] * sw[j + 2][e];  aN2 += sfn[j + 2] * sw[j + 2][e];
        aP3 += sfp[j + 3] * sw[j + 3][e];  aN3 += sfn[j + 3] * sw[j + 3][e];
    }
    g_chP[(b * NCHUNK + c) * EE + e] = (aP0 + aP1) + (aP2 + aP3);
    g_chN[(b * NCHUNK + c) * EE + e] = (aN0 + aN1) + (aN2 + aN3);
    if (e == 0) {
        float sP = 0.f, sN = 0.f;
        #pragma unroll
        for (int j = 0; j < CHUNK; j++) { sP += sfp[j]; sN += sfn[j]; }
        g_chPs[b * NCHUNK + c] = sP;
        g_chNs[b * NCHUNK + c] = sN;
    }
}

// ---------------- 4b. chunk-level offsets: unrolled vector scan + coop scalar scan ---
__global__ void __launch_bounds__(EE) k_offsets() {
    __shared__ float sN[NCHUNK], sP[NCHUNK];
    int b = blockIdx.x, e = threadIdx.x;   // 128 threads; NCHUNK == 128

    // vector forward scan (N), unroll 8 for MLP
    {
        float run = 0.f;
        for (int c = 0; c < NCHUNK; c += 8) {
            float v0 = g_chN[(b * NCHUNK + c + 0) * EE + e];
            float v1 = g_chN[(b * NCHUNK + c + 1) * EE + e];
            float v2 = g_chN[(b * NCHUNK + c + 2) * EE + e];
            float v3 = g_chN[(b * NCHUNK + c + 3) * EE + e];
            float v4 = g_chN[(b * NCHUNK + c + 4) * EE + e];
            float v5 = g_chN[(b * NCHUNK + c + 5) * EE + e];
            float v6 = g_chN[(b * NCHUNK + c + 6) * EE + e];
            float v7 = g_chN[(b * NCHUNK + c + 7) * EE + e];
            g_offN[(b * NCHUNK + c + 0) * EE + e] = run;
            g_offN[(b * NCHUNK + c + 1) * EE + e] = run + v0;
            g_offN[(b * NCHUNK + c + 2) * EE + e] = run + v0 + v1;
            g_offN[(b * NCHUNK + c + 3) * EE + e] = run + v0 + v1 + v2;
            float s4 = ((v0 + v1) + (v2 + v3));
            g_offN[(b * NCHUNK + c + 4) * EE + e] = run + s4;
            g_offN[(b * NCHUNK + c + 5) * EE + e] = run + s4 + v4;
            g_offN[(b * NCHUNK + c + 6) * EE + e] = run + s4 + v4 + v5;
            g_offN[(b * NCHUNK + c + 7) * EE + e] = run + s4 + v4 + v5 + v6;
            run += s4 + ((v4 + v5) + (v6 + v7));
        }
        g_preN[((size_t)b * (MM + 1) + MM) * EE + e] = run;
    }
    // vector backward scan (P), unroll 8
    {
        float run = 0.f;
        for (int c = NCHUNK - 8; c >= 0; c -= 8) {
            float v7 = g_chP[(b * NCHUNK + c + 7) * EE + e];
            float v6 = g_chP[(b * NCHUNK + c + 6) * EE + e];
            float v5 = g_chP[(b * NCHUNK + c + 5) * EE + e];
            float v4 = g_chP[(b * NCHUNK + c + 4) * EE + e];
            float v3 = g_chP[(b * NCHUNK + c + 3) * EE + e];
            float v2 = g_chP[(b * NCHUNK + c + 2) * EE + e];
            float v1 = g_chP[(b * NCHUNK + c + 1) * EE + e];
            float v0 = g_chP[(b * NCHUNK + c + 0) * EE + e];
            g_offP[(b * NCHUNK + c + 7) * EE + e] = run;
            g_offP[(b * NCHUNK + c + 6) * EE + e] = run + v7;
            g_offP[(b * NCHUNK + c + 5) * EE + e] = run + v7 + v6;
            g_offP[(b * NCHUNK + c + 4) * EE + e] = run + v7 + v6 + v5;
            float s4 = ((v7 + v6) + (v5 + v4));
            g_offP[(b * NCHUNK + c + 3) * EE + e] = run + s4;
            g_offP[(b * NCHUNK + c + 2) * EE + e] = run + s4 + v3;
            g_offP[(b * NCHUNK + c + 1) * EE + e] = run + s4 + v3 + v2;
            g_offP[(b * NCHUNK + c + 0) * EE + e] = run + s4 + v3 + v2 + v1;
            run += s4 + ((v3 + v2) + (v1 + v0));
        }
        g_sufP[((size_t)b * (MM + 1) + MM) * EE + e] = 0.f;
    }
    // cooperative scalar scans (Hillis-Steele over 128 chunks)
    float origN = g_chNs[b * NCHUNK + e];
    float origP = g_chPs[b * NCHUNK + e];
    sN[e] = origN;
    sP[e] = origP;
    __syncthreads();
    #pragma unroll
    for (int s = 1; s < NCHUNK; s <<= 1) {
        float tn = 0.f, tp = 0.f;
        if (e >= s) { tn = sN[e - s]; tp = sP[e - s]; }
        __syncthreads();
        sN[e] += tn;
        sP[e] += tp;
        __syncthreads();
    }
    float totalN = sN[NCHUNK - 1];
    float totalP = sP[NCHUNK - 1];
    g_offNs[b * NCHUNK + e] = sN[e] - origN;        // exclusive prefix
    g_offPs[b * NCHUNK + e] = totalP - sP[e];       // exclusive suffix
    if (e == 0) {
        g_preNs[b * (MM + 1) + MM] = totalN;
        g_sufPs[b * (MM + 1) + MM] = 0.f;
    }
}

// ---------------- 4c. fine-grained prefix (N) and suffix (P) sums (fp32) ------------
__global__ void __launch_bounds__(EE) k_scan() {
    __shared__ float sw[CHUNK][EE];
    __shared__ float sfp[CHUNK], sfn[CHUNK];
    __shared__ int   sm[CHUNK];
    int b = blockIdx.y, c = blockIdx.x, e = threadIdx.x;
    stage_chunk(b, c, e, sw, sfp, sfn, sm);

    // forward pass: prefix of F2n * Wh2
    {
        float runN  = g_offN[(b * NCHUNK + c) * EE + e];
        float runNs = (e == 0) ? g_offNs[b * NCHUNK + c] : 0.f;
        #pragma unroll
        for (int j = 0; j < CHUNK; j++) {
            int k = c * CHUNK + j;
            g_preN[((size_t)b * (MM + 1) + k) * EE + e] = runN;
            if (e == 0) g_preNs[b * (MM + 1) + k] = runNs;
            runN += sfn[j] * sw[j][e];
            if (e == 0) runNs += sfn[j];
        }
    }
    // backward pass: suffix of F2p * Wh2
    {
        float runP  = g_offP[(b * NCHUNK + c) * EE + e];
        float runPs = (e == 0) ? g_offPs[b * NCHUNK + c] : 0.f;
        #pragma unroll
        for (int j = CHUNK - 1; j >= 0; j--) {
            int k = c * CHUNK + j;
            runP += sfp[j] * sw[j][e];
            if (e == 0) runPs += sfp[j];
            g_sufP[((size_t)b * (MM + 1) + k) * EE + e] = runP;
            if (e == 0) g_sufPs[b * (MM + 1) + k] = runPs;
        }
    }
}

// ---------------- 5. fused rank + context + probs (8 rows per block) ----------------
__global__ void __launch_bounds__(512) k_rankprobs(float* __restrict__ out_ctx,
                                                   float* __restrict__ out_p) {
    __shared__ int   sk[8];
    __shared__ float sc1[8], sc2[8], skey[8];
    int g = blockIdx.x;            // 0 .. B*N/8 - 1
    int row0 = g * 8;
    int b = row0 >> 11;
    int tid = threadIdx.x;
    if (tid < 8) {
        int row = row0 + tid;
        float key = g_key[row];
        const float* sv = g_sortv + b * MM;
        int lo = 0, hi = MM;       // first index with sv[idx] > key
        while (lo < hi) {
            int mid = (lo + hi) >> 1;
            if (sv[mid] > key) hi = mid; else lo = mid + 1;
        }
        float E1p = g_E1p[row], E1n = g_E1n[row];
        float S = E1p * g_sufPs[b * (MM + 1) + lo] + E1n * g_preNs[b * (MM + 1) + lo];
        float invS = 1.f / S;
        sk[tid] = lo;
        sc1[tid] = E1p * invS;
        sc2[tid] = E1n * invS;
        skey[tid] = key;
    }
    __syncthreads();
    // context: 4 rows per pass, 2 passes
    {
        int e = tid & (EE - 1);
        int rb = tid >> 7;         // 0..3
        #pragma unroll
        for (int it = 0; it < 2; it++) {
            int r = it * 4 + rb;
            int row = row0 + r;
            int k = sk[r];
            float num = sc1[r] * g_sufP[((size_t)b * (MM + 1) + k) * EE + e]
                      + sc2[r] * g_preN[((size_t)b * (MM + 1) + k) * EE + e];
            out_ctx[(size_t)row * EE + e] = num;
        }
    }
    // probs: per-batch vectors held in registers, 8 output rows
    const float4 tv = ((const float4*)(g_att2 + b * MM))[tid];
    const float4 pv = ((const float4*)(g_F2p + b * MM))[tid];
    const float4 nv = ((const float4*)(g_F2n + b * MM))[tid];
    #pragma unroll
    for (int r = 0; r < 8; r++) {
        int row = row0 + r;
        float key = skey[r], c1 = sc1[r], c2 = sc2[r];
        float4 o;
        o.x = (tv.x > key) ? c1 * pv.x : c2 * nv.x;
        o.y = (tv.y > key) ? c1 * pv.y : c2 * nv.y;
        o.z = (tv.z > key) ? c1 * pv.z : c2 * nv.z;
        o.w = (tv.w > key) ? c1 * pv.w : c2 * nv.w;
        ((float4*)(out_p + (size_t)row * MM))[tid] = o;
    }
}

// ---------------- launch ----------------
extern "C" void kernel_launch(void* const* d_in, const int* in_sizes, int n_in,
                              void* d_out, int out_size) {
    const float* in1  = (const float*)d_in[0];   // (8,2048,256)
    const float* in2  = (const float*)d_in[1];   // (8,2048,256)
    const float* mask = (const float*)d_in[2];   // (8,1,2048)
    const float* W1   = (const float*)d_in[3];   // (256,128)
    const float* a1   = (const float*)d_in[4];   // (256,1)
    float* out = (float*)d_out;
    float* out_ctx   = out;                              // (8,2048,128)
    float* out_probs = out + (size_t)BB * NN * EE;       // (8,2048,2048)

    k_v<<<1, 256>>>(W1, a1);
    k_wh2<<<GEMM_BLOCKS + ATT1_BLOCKS, 256>>>(in2, W1, mask, a1, in1);
    k_sort<<<BB, 512>>>();
    dim3 gc(NCHUNK, BB);
    k_chunksum<<<gc, EE>>>();
    k_offsets<<<BB, EE>>>();
    k_scan<<<gc, EE>>>();
    k_rankprobs<<<BB * NN / 8, 512>>>(out_ctx, out_probs);
}

// round 11
// speedup vs baseline: 1.5072x; 1.0452x over previous
#include <cuda_runtime.h>
#include <cub/cub.cuh>

#define BB 8
#define NN 2048
#define MM 2048
#define DIN 256
#define EE 128
#define LALPHA 0.01f
#define NCHUNK 128
#define CHUNK 16            // MM / NCHUNK

#define GEMM_BLOCKS 256
#define ATT1_BLOCKS 2048    // B*N / 8 rows-per-block
#define RP_ROWS 16          // rows per k_rankprobs block

// ---------------- scratch (device globals; no allocation allowed) ----------------
__device__ float g_v1[DIN];
__device__ float g_att2[BB * MM];
__device__ float g_E1p[BB * NN], g_E1n[BB * NN], g_key[BB * NN];   // key = -att1
__device__ float g_F2p[BB * MM], g_F2n[BB * MM];
__device__ float g_Wh2[BB * MM * EE];
__device__ float g_sortv[BB * MM];
__device__ int   g_sortidx[BB * MM];
__device__ float g_chP[BB * NCHUNK * EE], g_chN[BB * NCHUNK * EE];
__device__ float g_chPs[BB * NCHUNK], g_chNs[BB * NCHUNK];
__device__ float g_offP[BB * NCHUNK * EE], g_offN[BB * NCHUNK * EE];
__device__ float g_offPs[BB * NCHUNK], g_offNs[BB * NCHUNK];
__device__ float g_sufP[BB * (MM + 1) * EE];   // suffix sums of F2p*Wh2 in sorted order
__device__ float g_preN[BB * (MM + 1) * EE];   // prefix sums of F2n*Wh2 in sorted order
__device__ float g_sufPs[BB * (MM + 1)], g_preNs[BB * (MM + 1)];

// ---------------- 1. v1 = W1 @ a1_top ----------------
__global__ void k_v(const float* __restrict__ W1, const float* __restrict__ a1) {
    int d = threadIdx.x;   // 0..255
    float s1 = 0.f;
    #pragma unroll 8
    for (int e = 0; e < EE; e++) s1 += W1[d * EE + e] * a1[e];
    g_v1[d] = s1;
}

// ---------------- 2. Wh2 GEMM via fma.f32x2 (blocks 0..255) + att1 (256..2303) -------
__global__ void __launch_bounds__(256) k_wh2(const float* __restrict__ in2,
                                             const float* __restrict__ W1,
                                             const float* __restrict__ mask,
                                             const float* __restrict__ a1,
                                             const float* __restrict__ in1) {
    __shared__ float As[64 * 32];
    __shared__ float Bs[32 * 128];
    int tid = threadIdx.x;

    if (blockIdx.x >= GEMM_BLOCKS) {
        // ---- att1 path: 8 warps, one row each ----
        int w    = (blockIdx.x - GEMM_BLOCKS) * 8 + (tid >> 5);   // 0 .. B*N-1
        int lane = tid & 31;
        const float4* p  = (const float4*)(in1 + (size_t)w * DIN);
        const float4* v4 = (const float4*)g_v1;
        float acc = 0.f;
        #pragma unroll
        for (int i = 0; i < 2; i++) {
            float4 x  = p[lane + 32 * i];
            float4 vv = v4[lane + 32 * i];
            acc += x.x * vv.x + x.y * vv.y + x.z * vv.z + x.w * vv.w;
        }
        #pragma unroll
        for (int o = 16; o > 0; o >>= 1) acc += __shfl_xor_sync(0xffffffffu, acc, o);
        if (lane == 0) {
            g_E1p[w] = expf(acc);
            g_E1n[w] = expf(LALPHA * acc);
            g_key[w] = -acc;
        }
        return;
    }

    // ---- GEMM path: 64 rows x 128 cols, K=256, packed f32x2 accumulators ----
    int tx = tid & 31;    // column group -> cols tx*4..tx*4+3
    int ty = tid >> 5;    // row group   -> rows ty*8..ty*8+7 (one warp per ty)
    int row0 = blockIdx.x * 64;
    uint64_t acc01[8], acc23[8];   // packed (col0,col1) and (col2,col3) per row
    #pragma unroll
    for (int r = 0; r < 8; r++) { acc01[r] = 0ull; acc23[r] = 0ull; }

    for (int k0 = 0; k0 < DIN; k0 += 32) {
        #pragma unroll
        for (int i = tid; i < 512; i += 256) {
            int r = i >> 3, kq = i & 7;
            ((float4*)As)[i] = *(const float4*)(in2 + (size_t)(row0 + r) * DIN + k0 + kq * 4);
        }
        #pragma unroll
        for (int i = tid; i < 1024; i += 256) {
            ((float4*)Bs)[i] = ((const float4*)(W1 + (size_t)k0 * EE))[i];
        }
        __syncthreads();
        const uint64_t* Bs64 = (const uint64_t*)Bs;   // 32 rows x 64 packed-pairs
        #pragma unroll
        for (int kk = 0; kk < 32; kk += 4) {
            uint64_t b01[4], b23[4];
            #pragma unroll
            for (int q = 0; q < 4; q++) {
                b01[q] = Bs64[(kk + q) * 64 + tx * 2 + 0];
                b23[q] = Bs64[(kk + q) * 64 + tx * 2 + 1];
            }
            #pragma unroll
            for (int r = 0; r < 8; r++) {
                float4 a4 = *(float4*)&As[(ty * 8 + r) * 32 + kk];   // warp-broadcast
                uint64_t aa;
                asm("mov.b64 %0, {%1, %1};" : "=l"(aa) : "f"(a4.x));
                asm("fma.rn.f32x2 %0, %1, %2, %0;" : "+l"(acc01[r]) : "l"(aa), "l"(b01[0]));
                asm("fma.rn.f32x2 %0, %1, %2, %0;" : "+l"(acc23[r]) : "l"(aa), "l"(b23[0]));
                asm("mov.b64 %0, {%1, %1};" : "=l"(aa) : "f"(a4.y));
                asm("fma.rn.f32x2 %0, %1, %2, %0;" : "+l"(acc01[r]) : "l"(aa), "l"(b01[1]));
                asm("fma.rn.f32x2 %0, %1, %2, %0;" : "+l"(acc23[r]) : "l"(aa), "l"(b23[1]));
                asm("mov.b64 %0, {%1, %1};" : "=l"(aa) : "f"(a4.z));
                asm("fma.rn.f32x2 %0, %1, %2, %0;" : "+l"(acc01[r]) : "l"(aa), "l"(b01[2]));
                asm("fma.rn.f32x2 %0, %1, %2, %0;" : "+l"(acc23[r]) : "l"(aa), "l"(b23[2]));
                asm("mov.b64 %0, {%1, %1};" : "=l"(aa) : "f"(a4.w));
                asm("fma.rn.f32x2 %0, %1, %2, %0;" : "+l"(acc01[r]) : "l"(aa), "l"(b01[3]));
                asm("fma.rn.f32x2 %0, %1, %2, %0;" : "+l"(acc23[r]) : "l"(aa), "l"(b23[3]));
            }
        }
        __syncthreads();
    }
    // epilogue: unpack, store Wh2, and compute att2 = Wh2 . a1[128:]
    float4 va = *(const float4*)(a1 + EE + tx * 4);
    #pragma unroll
    for (int r = 0; r < 8; r++) {
        float c0, c1, c2, c3;
        asm("mov.b64 {%0, %1}, %2;" : "=f"(c0), "=f"(c1) : "l"(acc01[r]));
        asm("mov.b64 {%0, %1}, %2;" : "=f"(c2), "=f"(c3) : "l"(acc23[r]));
        int row = row0 + ty * 8 + r;
        *(float4*)(g_Wh2 + (size_t)row * EE + tx * 4) = make_float4(c0, c1, c2, c3);
        float part = c0 * va.x + c1 * va.y + c2 * va.z + c3 * va.w;
        #pragma unroll
        for (int o = 16; o > 0; o >>= 1) part += __shfl_xor_sync(0xffffffffu, part, o);
        if (tx == 0) {
            int b = row >> 11, m = row & (MM - 1);
            float mk = mask[b * MM + m];
            g_att2[row] = part;
            g_F2p[row] = expf(part + mk);
            g_F2n[row] = expf(LALPHA * part + mk);
        }
    }
}

// ---------------- 3. per-batch radix sort of att2 (with index) ----------------
__global__ void __launch_bounds__(1024) k_sort() {
    typedef cub::BlockRadixSort<float, 1024, 2, int> Sorter;
    __shared__ typename Sorter::TempStorage tmp;
    int b = blockIdx.x;
    float key[2];
    int   val[2];
    #pragma unroll
    for (int i = 0; i < 2; i++) {
        int idx = threadIdx.x * 2 + i;
        key[i] = g_att2[b * MM + idx];
        val[i] = idx;
    }
    Sorter(tmp).Sort(key, val);
    #pragma unroll
    for (int i = 0; i < 2; i++) {
        int idx = threadIdx.x * 2 + i;
        g_sortv[b * MM + idx]   = key[i];
        g_sortidx[b * MM + idx] = val[i];
    }
}

// ---------------- staging helper: load one sorted chunk into smem ----------------
// Flat float4 gather: 4 independent coalesced LDG.128 per thread, no chain.
__device__ __forceinline__ void stage_chunk(int b, int c, int tid,
                                            float (*sw)[EE], float* sfp, float* sfn,
                                            int* sm) {
    int base = b * MM + c * CHUNK;
    if (tid < CHUNK) sm[tid] = g_sortidx[base + tid];
    __syncthreads();
    #pragma unroll
    for (int i = tid; i < CHUNK * 32; i += 128) {
        int row = i >> 5, c4 = i & 31;
        ((float4*)&sw[row][0])[c4] =
            ((const float4*)(g_Wh2 + (size_t)(b * MM + sm[row]) * EE))[c4];
    }
    if (tid < CHUNK) {
        sfp[tid] = g_F2p[b * MM + sm[tid]];
        sfn[tid] = g_F2n[b * MM + sm[tid]];
    }
    __syncthreads();
}

// ---------------- 4a. chunk partial sums (sorted order, fp32, smem-staged) ----------
__global__ void __launch_bounds__(EE) k_chunksum() {
    __shared__ float sw[CHUNK][EE];
    __shared__ float sfp[CHUNK], sfn[CHUNK];
    __shared__ int   sm[CHUNK];
    int b = blockIdx.y, c = blockIdx.x, e = threadIdx.x;
    stage_chunk(b, c, e, sw, sfp, sfn, sm);
    float aP0 = 0.f, aP1 = 0.f, aP2 = 0.f, aP3 = 0.f;
    float aN0 = 0.f, aN1 = 0.f, aN2 = 0.f, aN3 = 0.f;
    #pragma unroll
    for (int j = 0; j < CHUNK; j += 4) {
        aP0 += sfp[j + 0] * sw[j + 0][e];  aN0 += sfn[j + 0] * sw[j + 0][e];
        aP1 += sfp[j + 1] * sw[j + 1][e];  aN1 += sfn[j + 1] * sw[j + 1][e];
        aP2 += sfp[j + 2] * sw[j + 2][e];  aN2 += sfn[j + 2] * sw[j + 2][e];
        aP3 += sfp[j + 3] * sw[j + 3][e];  aN3 += sfn[j + 3] * sw[j + 3][e];
    }
    g_chP[(b * NCHUNK + c) * EE + e] = (aP0 + aP1) + (aP2 + aP3);
    g_chN[(b * NCHUNK + c) * EE + e] = (aN0 + aN1) + (aN2 + aN3);
    if (e == 0) {
        float sP = 0.f, sN = 0.f;
        #pragma unroll
        for (int j = 0; j < CHUNK; j++) { sP += sfp[j]; sN += sfn[j]; }
        g_chPs[b * NCHUNK + c] = sP;
        g_chNs[b * NCHUNK + c] = sN;
    }
}

// ---------------- 4b. chunk-level offsets: unrolled vector scan + coop scalar scan ---
__global__ void __launch_bounds__(EE) k_offsets() {
    __shared__ float sN[NCHUNK], sP[NCHUNK];
    int b = blockIdx.x, e = threadIdx.x;   // 128 threads; NCHUNK == 128

    // vector forward scan (N), unroll 8 for MLP
    {
        float run = 0.f;
        for (int c = 0; c < NCHUNK; c += 8) {
            float v0 = g_chN[(b * NCHUNK + c + 0) * EE + e];
            float v1 = g_chN[(b * NCHUNK + c + 1) * EE + e];
            float v2 = g_chN[(b * NCHUNK + c + 2) * EE + e];
            float v3 = g_chN[(b * NCHUNK + c + 3) * EE + e];
            float v4 = g_chN[(b * NCHUNK + c + 4) * EE + e];
            float v5 = g_chN[(b * NCHUNK + c + 5) * EE + e];
            float v6 = g_chN[(b * NCHUNK + c + 6) * EE + e];
            float v7 = g_chN[(b * NCHUNK + c + 7) * EE + e];
            g_offN[(b * NCHUNK + c + 0) * EE + e] = run;
            g_offN[(b * NCHUNK + c + 1) * EE + e] = run + v0;
            g_offN[(b * NCHUNK + c + 2) * EE + e] = run + v0 + v1;
            g_offN[(b * NCHUNK + c + 3) * EE + e] = run + v0 + v1 + v2;
            float s4 = ((v0 + v1) + (v2 + v3));
            g_offN[(b * NCHUNK + c + 4) * EE + e] = run + s4;
            g_offN[(b * NCHUNK + c + 5) * EE + e] = run + s4 + v4;
            g_offN[(b * NCHUNK + c + 6) * EE + e] = run + s4 + v4 + v5;
            g_offN[(b * NCHUNK + c + 7) * EE + e] = run + s4 + v4 + v5 + v6;
            run += s4 + ((v4 + v5) + (v6 + v7));
        }
        g_preN[((size_t)b * (MM + 1) + MM) * EE + e] = run;
    }
    // vector backward scan (P), unroll 8
    {
        float run = 0.f;
        for (int c = NCHUNK - 8; c >= 0; c -= 8) {
            float v7 = g_chP[(b * NCHUNK + c + 7) * EE + e];
            float v6 = g_chP[(b * NCHUNK + c + 6) * EE + e];
            float v5 = g_chP[(b * NCHUNK + c + 5) * EE + e];
            float v4 = g_chP[(b * NCHUNK + c + 4) * EE + e];
            float v3 = g_chP[(b * NCHUNK + c + 3) * EE + e];
            float v2 = g_chP[(b * NCHUNK + c + 2) * EE + e];
            float v1 = g_chP[(b * NCHUNK + c + 1) * EE + e];
            float v0 = g_chP[(b * NCHUNK + c + 0) * EE + e];
            g_offP[(b * NCHUNK + c + 7) * EE + e] = run;
            g_offP[(b * NCHUNK + c + 6) * EE + e] = run + v7;
            g_offP[(b * NCHUNK + c + 5) * EE + e] = run + v7 + v6;
            g_offP[(b * NCHUNK + c + 4) * EE + e] = run + v7 + v6 + v5;
            float s4 = ((v7 + v6) + (v5 + v4));
            g_offP[(b * NCHUNK + c + 3) * EE + e] = run + s4;
            g_offP[(b * NCHUNK + c + 2) * EE + e] = run + s4 + v3;
            g_offP[(b * NCHUNK + c + 1) * EE + e] = run + s4 + v3 + v2;
            g_offP[(b * NCHUNK + c + 0) * EE + e] = run + s4 + v3 + v2 + v1;
            run += s4 + ((v3 + v2) + (v1 + v0));
        }
        g_sufP[((size_t)b * (MM + 1) + MM) * EE + e] = 0.f;
    }
    // cooperative scalar scans (Hillis-Steele over 128 chunks)
    float origN = g_chNs[b * NCHUNK + e];
    float origP = g_chPs[b * NCHUNK + e];
    sN[e] = origN;
    sP[e] = origP;
    __syncthreads();
    #pragma unroll
    for (int s = 1; s < NCHUNK; s <<= 1) {
        float tn = 0.f, tp = 0.f;
        if (e >= s) { tn = sN[e - s]; tp = sP[e - s]; }
        __syncthreads();
        sN[e] += tn;
        sP[e] += tp;
        __syncthreads();
    }
    float totalN = sN[NCHUNK - 1];
    float totalP = sP[NCHUNK - 1];
    g_offNs[b * NCHUNK + e] = sN[e] - origN;        // exclusive prefix
    g_offPs[b * NCHUNK + e] = totalP - sP[e];       // exclusive suffix
    if (e == 0) {
        g_preNs[b * (MM + 1) + MM] = totalN;
        g_sufPs[b * (MM + 1) + MM] = 0.f;
    }
}

// ---------------- 4c. fine-grained prefix (N) and suffix (P) sums (fp32) ------------
__global__ void __launch_bounds__(EE) k_scan() {
    __shared__ float sw[CHUNK][EE];
    __shared__ float sfp[CHUNK], sfn[CHUNK];
    __shared__ int   sm[CHUNK];
    int b = blockIdx.y, c = blockIdx.x, e = threadIdx.x;
    stage_chunk(b, c, e, sw, sfp, sfn, sm);

    // forward pass: prefix of F2n * Wh2
    {
        float runN  = g_offN[(b * NCHUNK + c) * EE + e];
        float runNs = (e == 0) ? g_offNs[b * NCHUNK + c] : 0.f;
        #pragma unroll
        for (int j = 0; j < CHUNK; j++) {
            int k = c * CHUNK + j;
            g_preN[((size_t)b * (MM + 1) + k) * EE + e] = runN;
            if (e == 0) g_preNs[b * (MM + 1) + k] = runNs;
            runN += sfn[j] * sw[j][e];
            if (e == 0) runNs += sfn[j];
        }
    }
    // backward pass: suffix of F2p * Wh2
    {
        float runP  = g_offP[(b * NCHUNK + c) * EE + e];
        float runPs = (e == 0) ? g_offPs[b * NCHUNK + c] : 0.f;
        #pragma unroll
        for (int j = CHUNK - 1; j >= 0; j--) {
            int k = c * CHUNK + j;
            runP += sfp[j] * sw[j][e];
            if (e == 0) runPs += sfp[j];
            g_sufP[((size_t)b * (MM + 1) + k) * EE + e] = runP;
            if (e == 0) g_sufPs[b * (MM + 1) + k] = runPs;
        }
    }
}

// ---------------- 5. fused rank + context + probs (16 rows per block) ----------------
__global__ void __launch_bounds__(512) k_rankprobs(float* __restrict__ out_ctx,
                                                   float* __restrict__ out_p) {
    __shared__ int   sk[RP_ROWS];
    __shared__ float sc1[RP_ROWS], sc2[RP_ROWS], skey[RP_ROWS];
    int g = blockIdx.x;            // 0 .. B*N/RP_ROWS - 1
    int row0 = g * RP_ROWS;
    int b = row0 >> 11;
    int tid = threadIdx.x;
    if (tid < RP_ROWS) {
        int row = row0 + tid;
        float key = g_key[row];
        const float* sv = g_sortv + b * MM;
        int lo = 0, hi = MM;       // first index with sv[idx] > key
        while (lo < hi) {
            int mid = (lo + hi) >> 1;
            if (sv[mid] > key) hi = mid; else lo = mid + 1;
        }
        float E1p = g_E1p[row], E1n = g_E1n[row];
        float S = E1p * g_sufPs[b * (MM + 1) + lo] + E1n * g_preNs[b * (MM + 1) + lo];
        float invS = 1.f / S;
        sk[tid] = lo;
        sc1[tid] = E1p * invS;
        sc2[tid] = E1n * invS;
        skey[tid] = key;
    }
    __syncthreads();
    // context: 4 rows per pass, 4 passes
    {
        int e = tid & (EE - 1);
        int rb = tid >> 7;         // 0..3
        #pragma unroll
        for (int it = 0; it < RP_ROWS / 4; it++) {
            int r = it * 4 + rb;
            int row = row0 + r;
            int k = sk[r];
            float num = sc1[r] * g_sufP[((size_t)b * (MM + 1) + k) * EE + e]
                      + sc2[r] * g_preN[((size_t)b * (MM + 1) + k) * EE + e];
            out_ctx[(size_t)row * EE + e] = num;
        }
    }
    // probs: per-batch vectors held in registers, RP_ROWS output rows (streaming stores)
    const float4 tv = ((const float4*)(g_att2 + b * MM))[tid];
    const float4 pv = ((const float4*)(g_F2p + b * MM))[tid];
    const float4 nv = ((const float4*)(g_F2n + b * MM))[tid];
    #pragma unroll
    for (int r = 0; r < RP_ROWS; r++) {
        int row = row0 + r;
        float key = skey[r], c1 = sc1[r], c2 = sc2[r];
        float4 o;
        o.x = (tv.x > key) ? c1 * pv.x : c2 * nv.x;
        o.y = (tv.y > key) ? c1 * pv.y : c2 * nv.y;
        o.z = (tv.z > key) ? c1 * pv.z : c2 * nv.z;
        o.w = (tv.w > key) ? c1 * pv.w : c2 * nv.w;
        __stcs((float4*)(out_p + (size_t)row * MM) + tid, o);
    }
}

// ---------------- launch ----------------
extern "C" void kernel_launch(void* const* d_in, const int* in_sizes, int n_in,
                              void* d_out, int out_size) {
    const float* in1  = (const float*)d_in[0];   // (8,2048,256)
    const float* in2  = (const float*)d_in[1];   // (8,2048,256)
    const float* mask = (const float*)d_in[2];   // (8,1,2048)
    const float* W1   = (const float*)d_in[3];   // (256,128)
    const float* a1   = (const float*)d_in[4];   // (256,1)
    float* out = (float*)d_out;
    float* out_ctx   = out;                              // (8,2048,128)
    float* out_probs = out + (size_t)BB * NN * EE;       // (8,2048,2048)

    k_v<<<1, 256>>>(W1, a1);
    k_wh2<<<GEMM_BLOCKS + ATT1_BLOCKS, 256>>>(in2, W1, mask, a1, in1);
    k_sort<<<BB, 1024>>>();
    dim3 gc(NCHUNK, BB);
    k_chunksum<<<gc, EE>>>();
    k_offsets<<<BB, EE>>>();
    k_scan<<<gc, EE>>>();
    k_rankprobs<<<BB * NN / RP_ROWS, 512>>>(out_ctx, out_probs);
}

// round 12
// speedup vs baseline: 1.5440x; 1.0244x over previous
#include <cuda_runtime.h>
#include <cub/cub.cuh>

#define BB 8
#define NN 2048
#define MM 2048
#define DIN 256
#define EE 128
#define LALPHA 0.01f
#define NCHUNK 128
#define CHUNK 16            // MM / NCHUNK

#define GEMM_BLOCKS 256
#define ATT1_BLOCKS 2048    // B*N / 8 rows-per-block
#define RP_ROWS 16          // rows per k_rankprobs block

// ---------------- scratch (device globals; no allocation allowed) ----------------
__device__ float g_v1[DIN];
__device__ float g_att2[BB * MM];
__device__ float g_E1p[BB * NN], g_E1n[BB * NN], g_key[BB * NN];   // key = -att1
__device__ float g_F2p[BB * MM], g_F2n[BB * MM];
__device__ float g_Wh2[BB * MM * EE];
__device__ float g_sortv[BB * MM];
__device__ int   g_sortidx[BB * MM];
__device__ float g_chP[BB * NCHUNK * EE], g_chN[BB * NCHUNK * EE];   // chunk totals
__device__ float g_chPs[BB * NCHUNK], g_chNs[BB * NCHUNK];
__device__ float g_offP[BB * (NCHUNK + 1) * EE], g_offN[BB * (NCHUNK + 1) * EE];
__device__ float g_offPs[BB * (NCHUNK + 1)], g_offNs[BB * (NCHUNK + 1)];
__device__ float g_sufP[BB * (MM + 1) * EE];   // chunk-LOCAL suffix of F2p*Wh2 (sorted)
__device__ float g_preN[BB * (MM + 1) * EE];   // chunk-LOCAL prefix of F2n*Wh2 (sorted)
__device__ float g_sufPs[BB * (MM + 1)], g_preNs[BB * (MM + 1)];

// ---------------- 1. v1 = W1 @ a1_top ----------------
__global__ void k_v(const float* __restrict__ W1, const float* __restrict__ a1) {
    int d = threadIdx.x;   // 0..255
    float s1 = 0.f;
    #pragma unroll 8
    for (int e = 0; e < EE; e++) s1 += W1[d * EE + e] * a1[e];
    g_v1[d] = s1;
}

// ---------------- 2. Wh2 GEMM via fma.f32x2 (blocks 0..255) + att1 (256..2303) -------
__global__ void __launch_bounds__(256) k_wh2(const float* __restrict__ in2,
                                             const float* __restrict__ W1,
                                             const float* __restrict__ mask,
                                             const float* __restrict__ a1,
                                             const float* __restrict__ in1) {
    __shared__ float As[64 * 32];
    __shared__ float Bs[32 * 128];
    int tid = threadIdx.x;

    if (blockIdx.x >= GEMM_BLOCKS) {
        // ---- att1 path: 8 warps, one row each ----
        int w    = (blockIdx.x - GEMM_BLOCKS) * 8 + (tid >> 5);   // 0 .. B*N-1
        int lane = tid & 31;
        const float4* p  = (const float4*)(in1 + (size_t)w * DIN);
        const float4* v4 = (const float4*)g_v1;
        float acc = 0.f;
        #pragma unroll
        for (int i = 0; i < 2; i++) {
            float4 x  = p[lane + 32 * i];
            float4 vv = v4[lane + 32 * i];
            acc += x.x * vv.x + x.y * vv.y + x.z * vv.z + x.w * vv.w;
        }
        #pragma unroll
        for (int o = 16; o > 0; o >>= 1) acc += __shfl_xor_sync(0xffffffffu, acc, o);
        if (lane == 0) {
            g_E1p[w] = expf(acc);
            g_E1n[w] = expf(LALPHA * acc);
            g_key[w] = -acc;
        }
        return;
    }

    // ---- GEMM path: 64 rows x 128 cols, K=256, packed f32x2 accumulators ----
    int tx = tid & 31;    // column group -> cols tx*4..tx*4+3
    int ty = tid >> 5;    // row group   -> rows ty*8..ty*8+7 (one warp per ty)
    int row0 = blockIdx.x * 64;
    uint64_t acc01[8], acc23[8];   // packed (col0,col1) and (col2,col3) per row
    #pragma unroll
    for (int r = 0; r < 8; r++) { acc01[r] = 0ull; acc23[r] = 0ull; }

    for (int k0 = 0; k0 < DIN; k0 += 32) {
        #pragma unroll
        for (int i = tid; i < 512; i += 256) {
            int r = i >> 3, kq = i & 7;
            ((float4*)As)[i] = *(const float4*)(in2 + (size_t)(row0 + r) * DIN + k0 + kq * 4);
        }
        #pragma unroll
        for (int i = tid; i < 1024; i += 256) {
            ((float4*)Bs)[i] = ((const float4*)(W1 + (size_t)k0 * EE))[i];
        }
        __syncthreads();
        const uint64_t* Bs64 = (const uint64_t*)Bs;   // 32 rows x 64 packed-pairs
        #pragma unroll
        for (int kk = 0; kk < 32; kk += 4) {
            uint64_t b01[4], b23[4];
            #pragma unroll
            for (int q = 0; q < 4; q++) {
                b01[q] = Bs64[(kk + q) * 64 + tx * 2 + 0];
                b23[q] = Bs64[(kk + q) * 64 + tx * 2 + 1];
            }
            #pragma unroll
            for (int r = 0; r < 8; r++) {
                float4 a4 = *(float4*)&As[(ty * 8 + r) * 32 + kk];   // warp-broadcast
                uint64_t aa;
                asm("mov.b64 %0, {%1, %1};" : "=l"(aa) : "f"(a4.x));
                asm("fma.rn.f32x2 %0, %1, %2, %0;" : "+l"(acc01[r]) : "l"(aa), "l"(b01[0]));
                asm("fma.rn.f32x2 %0, %1, %2, %0;" : "+l"(acc23[r]) : "l"(aa), "l"(b23[0]));
                asm("mov.b64 %0, {%1, %1};" : "=l"(aa) : "f"(a4.y));
                asm("fma.rn.f32x2 %0, %1, %2, %0;" : "+l"(acc01[r]) : "l"(aa), "l"(b01[1]));
                asm("fma.rn.f32x2 %0, %1, %2, %0;" : "+l"(acc23[r]) : "l"(aa), "l"(b23[1]));
                asm("mov.b64 %0, {%1, %1};" : "=l"(aa) : "f"(a4.z));
                asm("fma.rn.f32x2 %0, %1, %2, %0;" : "+l"(acc01[r]) : "l"(aa), "l"(b01[2]));
                asm("fma.rn.f32x2 %0, %1, %2, %0;" : "+l"(acc23[r]) : "l"(aa), "l"(b23[2]));
                asm("mov.b64 %0, {%1, %1};" : "=l"(aa) : "f"(a4.w));
                asm("fma.rn.f32x2 %0, %1, %2, %0;" : "+l"(acc01[r]) : "l"(aa), "l"(b01[3]));
                asm("fma.rn.f32x2 %0, %1, %2, %0;" : "+l"(acc23[r]) : "l"(aa), "l"(b23[3]));
            }
        }
        __syncthreads();
    }
    // epilogue: unpack, store Wh2, and compute att2 = Wh2 . a1[128:]
    float4 va = *(const float4*)(a1 + EE + tx * 4);
    #pragma unroll
    for (int r = 0; r < 8; r++) {
        float c0, c1, c2, c3;
        asm("mov.b64 {%0, %1}, %2;" : "=f"(c0), "=f"(c1) : "l"(acc01[r]));
        asm("mov.b64 {%0, %1}, %2;" : "=f"(c2), "=f"(c3) : "l"(acc23[r]));
        int row = row0 + ty * 8 + r;
        *(float4*)(g_Wh2 + (size_t)row * EE + tx * 4) = make_float4(c0, c1, c2, c3);
        float part = c0 * va.x + c1 * va.y + c2 * va.z + c3 * va.w;
        #pragma unroll
        for (int o = 16; o > 0; o >>= 1) part += __shfl_xor_sync(0xffffffffu, part, o);
        if (tx == 0) {
            int b = row >> 11, m = row & (MM - 1);
            float mk = mask[b * MM + m];
            g_att2[row] = part;
            g_F2p[row] = expf(part + mk);
            g_F2n[row] = expf(LALPHA * part + mk);
        }
    }
}

// ---------------- 3. per-batch radix sort of att2 (with index) ----------------
__global__ void __launch_bounds__(1024) k_sort() {
    typedef cub::BlockRadixSort<float, 1024, 2, int> Sorter;
    __shared__ typename Sorter::TempStorage tmp;
    int b = blockIdx.x;
    float key[2];
    int   val[2];
    #pragma unroll
    for (int i = 0; i < 2; i++) {
        int idx = threadIdx.x * 2 + i;
        key[i] = g_att2[b * MM + idx];
        val[i] = idx;
    }
    Sorter(tmp).Sort(key, val);
    #pragma unroll
    for (int i = 0; i < 2; i++) {
        int idx = threadIdx.x * 2 + i;
        g_sortv[b * MM + idx]   = key[i];
        g_sortidx[b * MM + idx] = val[i];
    }
}

// ---------------- staging helper: load one sorted chunk into smem ----------------
__device__ __forceinline__ void stage_chunk(int b, int c, int tid,
                                            float (*sw)[EE], float* sfp, float* sfn,
                                            int* sm) {
    int base = b * MM + c * CHUNK;
    if (tid < CHUNK) sm[tid] = g_sortidx[base + tid];
    __syncthreads();
    #pragma unroll
    for (int i = tid; i < CHUNK * 32; i += 128) {
        int row = i >> 5, c4 = i & 31;
        ((float4*)&sw[row][0])[c4] =
            ((const float4*)(g_Wh2 + (size_t)(b * MM + sm[row]) * EE))[c4];
    }
    if (tid < CHUNK) {
        sfp[tid] = g_F2p[b * MM + sm[tid]];
        sfn[tid] = g_F2n[b * MM + sm[tid]];
    }
    __syncthreads();
}

// ---------------- 4a. chunk-LOCAL prefix (N) / suffix (P) + chunk totals ------------
__global__ void __launch_bounds__(EE) k_scan() {
    __shared__ float sw[CHUNK][EE];
    __shared__ float sfp[CHUNK], sfn[CHUNK];
    __shared__ int   sm[CHUNK];
    int b = blockIdx.y, c = blockIdx.x, e = threadIdx.x;
    stage_chunk(b, c, e, sw, sfp, sfn, sm);

    // forward pass: local prefix of F2n * Wh2 (starts at 0)
    {
        float runN  = 0.f;
        float runNs = 0.f;
        #pragma unroll
        for (int j = 0; j < CHUNK; j++) {
            int k = c * CHUNK + j;
            g_preN[((size_t)b * (MM + 1) + k) * EE + e] = runN;
            if (e == 0) g_preNs[b * (MM + 1) + k] = runNs;
            runN += sfn[j] * sw[j][e];
            if (e == 0) runNs += sfn[j];
        }
        g_chN[(b * NCHUNK + c) * EE + e] = runN;         // chunk total
        if (e == 0) g_chNs[b * NCHUNK + c] = runNs;
    }
    // backward pass: local suffix of F2p * Wh2 (starts at 0)
    {
        float runP  = 0.f;
        float runPs = 0.f;
        #pragma unroll
        for (int j = CHUNK - 1; j >= 0; j--) {
            int k = c * CHUNK + j;
            runP += sfp[j] * sw[j][e];
            if (e == 0) runPs += sfp[j];
            g_sufP[((size_t)b * (MM + 1) + k) * EE + e] = runP;
            if (e == 0) g_sufPs[b * (MM + 1) + k] = runPs;
        }
        g_chP[(b * NCHUNK + c) * EE + e] = runP;         // chunk total
        if (e == 0) g_chPs[b * NCHUNK + c] = runPs;
    }
}

// ---------------- 4b. chunk-level offsets (incl. sentinel entry NCHUNK) -------------
__global__ void __launch_bounds__(EE) k_offsets() {
    __shared__ float sN[NCHUNK], sP[NCHUNK];
    int b = blockIdx.x, e = threadIdx.x;   // 128 threads; NCHUNK == 128

    // vector forward scan (N), unroll 8 for MLP
    {
        float run = 0.f;
        for (int c = 0; c < NCHUNK; c += 8) {
            float v0 = g_chN[(b * NCHUNK + c + 0) * EE + e];
            float v1 = g_chN[(b * NCHUNK + c + 1) * EE + e];
            float v2 = g_chN[(b * NCHUNK + c + 2) * EE + e];
            float v3 = g_chN[(b * NCHUNK + c + 3) * EE + e];
            float v4 = g_chN[(b * NCHUNK + c + 4) * EE + e];
            float v5 = g_chN[(b * NCHUNK + c + 5) * EE + e];
            float v6 = g_chN[(b * NCHUNK + c + 6) * EE + e];
            float v7 = g_chN[(b * NCHUNK + c + 7) * EE + e];
            g_offN[(b * (NCHUNK + 1) + c + 0) * EE + e] = run;
            g_offN[(b * (NCHUNK + 1) + c + 1) * EE + e] = run + v0;
            g_offN[(b * (NCHUNK + 1) + c + 2) * EE + e] = run + v0 + v1;
            g_offN[(b * (NCHUNK + 1) + c + 3) * EE + e] = run + v0 + v1 + v2;
            float s4 = ((v0 + v1) + (v2 + v3));
            g_offN[(b * (NCHUNK + 1) + c + 4) * EE + e] = run + s4;
            g_offN[(b * (NCHUNK + 1) + c + 5) * EE + e] = run + s4 + v4;
            g_offN[(b * (NCHUNK + 1) + c + 6) * EE + e] = run + s4 + v4 + v5;
            g_offN[(b * (NCHUNK + 1) + c + 7) * EE + e] = run + s4 + v4 + v5 + v6;
            run += s4 + ((v4 + v5) + (v6 + v7));
        }
        g_offN[(b * (NCHUNK + 1) + NCHUNK) * EE + e] = run;   // sentinel = total
    }
    // vector backward scan (P), unroll 8
    {
        float run = 0.f;
        g_offP[(b * (NCHUNK + 1) + NCHUNK) * EE + e] = 0.f;   // sentinel
        for (int c = NCHUNK - 8; c >= 0; c -= 8) {
            float v7 = g_chP[(b * NCHUNK + c + 7) * EE + e];
            float v6 = g_chP[(b * NCHUNK + c + 6) * EE + e];
            float v5 = g_chP[(b * NCHUNK + c + 5) * EE + e];
            float v4 = g_chP[(b * NCHUNK + c + 4) * EE + e];
            float v3 = g_chP[(b * NCHUNK + c + 3) * EE + e];
            float v2 = g_chP[(b * NCHUNK + c + 2) * EE + e];
            float v1 = g_chP[(b * NCHUNK + c + 1) * EE + e];
            float v0 = g_chP[(b * NCHUNK + c + 0) * EE + e];
            g_offP[(b * (NCHUNK + 1) + c + 7) * EE + e] = run;
            g_offP[(b * (NCHUNK + 1) + c + 6) * EE + e] = run + v7;
            g_offP[(b * (NCHUNK + 1) + c + 5) * EE + e] = run + v7 + v6;
            g_offP[(b * (NCHUNK + 1) + c + 4) * EE + e] = run + v7 + v6 + v5;
            float s4 = ((v7 + v6) + (v5 + v4));
            g_offP[(b * (NCHUNK + 1) + c + 3) * EE + e] = run + s4;
            g_offP[(b * (NCHUNK + 1) + c + 2) * EE + e] = run + s4 + v3;
            g_offP[(b * (NCHUNK + 1) + c + 1) * EE + e] = run + s4 + v3 + v2;
            g_offP[(b * (NCHUNK + 1) + c + 0) * EE + e] = run + s4 + v3 + v2 + v1;
            run += s4 + ((v3 + v2) + (v1 + v0));
        }
    }
    // zero local sentinels at k = MM (so local+offset composition is exact there)
    g_preN[((size_t)b * (MM + 1) + MM) * EE + e] = 0.f;
    g_sufP[((size_t)b * (MM + 1) + MM) * EE + e] = 0.f;

    // cooperative scalar scans (Hillis-Steele over 128 chunks)
    float origN = g_chNs[b * NCHUNK + e];
    float origP = g_chPs[b * NCHUNK + e];
    sN[e] = origN;
    sP[e] = origP;
    __syncthreads();
    #pragma unroll
    for (int s = 1; s < NCHUNK; s <<= 1) {
        float tn = 0.f, tp = 0.f;
        if (e >= s) { tn = sN[e - s]; tp = sP[e - s]; }
        __syncthreads();
        sN[e] += tn;
        sP[e] += tp;
        __syncthreads();
    }
    float totalN = sN[NCHUNK - 1];
    float totalP = sP[NCHUNK - 1];
    g_offNs[b * (NCHUNK + 1) + e] = sN[e] - origN;        // exclusive prefix
    g_offPs[b * (NCHUNK + 1) + e] = totalP - sP[e];       // exclusive suffix
    if (e == 0) {
        g_offNs[b * (NCHUNK + 1) + NCHUNK] = totalN;      // sentinel
        g_offPs[b * (NCHUNK + 1) + NCHUNK] = 0.f;
        g_preNs[b * (MM + 1) + MM] = 0.f;                 // local sentinels
        g_sufPs[b * (MM + 1) + MM] = 0.f;
    }
}

// ---------------- 5. fused rank + context + probs (16 rows per block) ----------------
__global__ void __launch_bounds__(512) k_rankprobs(float* __restrict__ out_ctx,
                                                   float* __restrict__ out_p) {
    __shared__ int   sk[RP_ROWS], sc[RP_ROWS];
    __shared__ float sc1[RP_ROWS], sc2[RP_ROWS], skey[RP_ROWS];
    int g = blockIdx.x;            // 0 .. B*N/RP_ROWS - 1
    int row0 = g * RP_ROWS;
    int b = row0 >> 11;
    int tid = threadIdx.x;
    if (tid < RP_ROWS) {
        int row = row0 + tid;
        float key = g_key[row];
        const float* sv = g_sortv + b * MM;
        int lo = 0, hi = MM;       // first index with sv[idx] > key
        while (lo < hi) {
            int mid = (lo + hi) >> 1;
            if (sv[mid] > key) hi = mid; else lo = mid + 1;
        }
        int c = lo >> 4;           // CHUNK == 16 (c in [0, NCHUNK])
        float E1p = g_E1p[row], E1n = g_E1n[row];
        float sufPs = g_sufPs[b * (MM + 1) + lo] + g_offPs[b * (NCHUNK + 1) + c];
        float preNs = g_preNs[b * (MM + 1) + lo] + g_offNs[b * (NCHUNK + 1) + c];
        float S = E1p * sufPs + E1n * preNs;
        float invS = 1.f / S;
        sk[tid] = lo;
        sc[tid] = c;
        sc1[tid] = E1p * invS;
        sc2[tid] = E1n * invS;
        skey[tid] = key;
    }
    __syncthreads();
    // context: 4 rows per pass, 4 passes
    {
        int e = tid & (EE - 1);
        int rb = tid >> 7;         // 0..3
        #pragma unroll
        for (int it = 0; it < RP_ROWS / 4; it++) {
            int r = it * 4 + rb;
            int row = row0 + r;
            int k = sk[r], c = sc[r];
            float sufP = g_sufP[((size_t)b * (MM + 1) + k) * EE + e]
                       + g_offP[(b * (NCHUNK + 1) + c) * EE + e];
            float preN = g_preN[((size_t)b * (MM + 1) + k) * EE + e]
                       + g_offN[(b * (NCHUNK + 1) + c) * EE + e];
            out_ctx[(size_t)row * EE + e] = sc1[r] * sufP + sc2[r] * preN;
        }
    }
    // probs: per-batch vectors held in registers, RP_ROWS output rows (streaming stores)
    const float4 tv = ((const float4*)(g_att2 + b * MM))[tid];
    const float4 pv = ((const float4*)(g_F2p + b * MM))[tid];
    const float4 nv = ((const float4*)(g_F2n + b * MM))[tid];
    #pragma unroll
    for (int r = 0; r < RP_ROWS; r++) {
        int row = row0 + r;
        float key = skey[r], c1 = sc1[r], c2 = sc2[r];
        float4 o;
        o.x = (tv.x > key) ? c1 * pv.x : c2 * nv.x;
        o.y = (tv.y > key) ? c1 * pv.y : c2 * nv.y;
        o.z = (tv.z > key) ? c1 * pv.z : c2 * nv.z;
        o.w = (tv.w > key) ? c1 * pv.w : c2 * nv.w;
        __stcs((float4*)(out_p + (size_t)row * MM) + tid, o);
    }
}

// ---------------- launch ----------------
extern "C" void kernel_launch(void* const* d_in, const int* in_sizes, int n_in,
                              void* d_out, int out_size) {
    const float* in1  = (const float*)d_in[0];   // (8,2048,256)
    const float* in2  = (const float*)d_in[1];   // (8,2048,256)
    const float* mask = (const float*)d_in[2];   // (8,1,2048)
    const float* W1   = (const float*)d_in[3];   // (256,128)
    const float* a1   = (const float*)d_in[4];   // (256,1)
    float* out = (float*)d_out;
    float* out_ctx   = out;                              // (8,2048,128)
    float* out_probs = out + (size_t)BB * NN * EE;       // (8,2048,2048)

    k_v<<<1, 256>>>(W1, a1);
    k_wh2<<<GEMM_BLOCKS + ATT1_BLOCKS, 256>>>(in2, W1, mask, a1, in1);
    k_sort<<<BB, 1024>>>();
    dim3 gc(NCHUNK, BB);
    k_scan<<<gc, EE>>>();
    k_offsets<<<BB, EE>>>();
    k_rankprobs<<<BB * NN / RP_ROWS, 512>>>(out_ctx, out_probs);
}